// round 7
// baseline (speedup 1.0000x reference)
#include <cuda_runtime.h>
#include <math.h>

#define NN 50000
#define EE 800000
#define F_STATS 1
#define F_BIAS  2
#define F_POOL  4

// ------------------------- static device scratch (zero-init BSS) -------------------------
__device__ float g_stem[NN * 192];
__device__ float g_cell[2][NN * 256];
__device__ float g_ab[2][NN * 64];
__device__ float g_x0[NN * 64];
__device__ float g_tmp[NN * 192];
__device__ float g_aggS[5][NN * 64];
__device__ float g_aggN[5][NN * 64];
__device__ float g_enorm[EE];
__device__ int   g_esrc[EE];
__device__ int   g_cnt[NN];
__device__ int   g_rptr[NN + 1];
__device__ int   g_fill[NN];
__device__ float g_invdeg[NN];
__device__ float g_invsqrt[NN];
__device__ float g_pooled[NN];
__device__ float g_colsum[256];
__device__ float g_colsq[256];
__device__ float g_mu[256];
__device__ float g_rsd[256];
__device__ float g_wmix[14 * 8];
__device__ float g_Wprep[28 * 7 * 4096];

// ------------------------- graph preprocessing -------------------------
__global__ void zero_cnt_kernel() {
    int i = blockIdx.x * blockDim.x + threadIdx.x;
    if (i < NN) g_cnt[i] = 0;
}

__global__ void deg_kernel(const int* __restrict__ dst) {
    int e = blockIdx.x * blockDim.x + threadIdx.x;
    if (e < EE) atomicAdd(&g_cnt[dst[e]], 1);
}

__global__ void scan_kernel() {
    __shared__ int sh[1024];
    int carry = 0;
    for (int base = 0; base < NN; base += 1024) {
        int i = base + (int)threadIdx.x;
        int v = (i < NN) ? g_cnt[i] : 0;
        sh[threadIdx.x] = v;
        __syncthreads();
        for (int off = 1; off < 1024; off <<= 1) {
            int t = (threadIdx.x >= off) ? sh[threadIdx.x - off] : 0;
            __syncthreads();
            sh[threadIdx.x] += t;
            __syncthreads();
        }
        int incl = sh[threadIdx.x];
        if (i < NN) {
            int excl = carry + incl - v;
            g_rptr[i] = excl;
            g_fill[i] = excl;
            float d = (float)(v > 0 ? v : 1);
            g_invdeg[i]  = 1.0f / d;
            g_invsqrt[i] = rsqrtf(d);
        }
        carry += sh[1023];
        __syncthreads();
    }
    if (threadIdx.x == 0) g_rptr[NN] = carry;
}

__global__ void scatter_kernel(const int* __restrict__ src, const int* __restrict__ dst) {
    int e = blockIdx.x * blockDim.x + threadIdx.x;
    if (e >= EE) return;
    int s = src[e], d = dst[e];
    int pos = atomicAdd(&g_fill[d], 1);
    g_esrc[pos]  = s;
    g_enorm[pos] = g_invsqrt[s] * g_invsqrt[d];
}

// ------------------------- alpha softmax + fused weight prep -------------------------
__global__ void softmax_kernel(const float* __restrict__ a) {
    int r = threadIdx.x;
    if (r >= 14) return;
    float m = -1e30f;
    for (int j = 0; j < 8; j++) m = fmaxf(m, a[r * 8 + j]);
    float e[8], s = 0.f;
    for (int j = 0; j < 8; j++) { e[j] = expf(a[r * 8 + j] - m); s += e[j]; }
    float inv = 1.f / s;
    for (int j = 0; j < 8; j++) g_wmix[r * 8 + j] = e[j] * inv;
}

__global__ void prep_kernel(const float* __restrict__ Wgcn, const float* __restrict__ Wss,
                            const float* __restrict__ Wsn,  const float* __restrict__ Wgin,
                            const float* __restrict__ Wgc1, const float* __restrict__ Wgc2,
                            const float* __restrict__ Wmlp, const float* __restrict__ Wgcnii) {
    int slot = blockIdx.x;                       // ci*14 + ej
    int ej   = slot % 14;
    int idx  = blockIdx.y * 256 + threadIdx.x;   // 0..4095
    int r = idx >> 6, c = idx & 63;
    const float* wv = g_wmix + ej * 8;
    size_t in = (size_t)slot * 4096 + idx;
    size_t ob = (size_t)slot * 7 * 4096;
    g_Wprep[ob + 0 * 4096 + idx] = wv[1] * (r == c ? 1.f : 0.f) + wv[3] * Wss[in] + wv[5] * Wgc1[in];
    g_Wprep[ob + 1 * 4096 + idx] = wv[3] * Wsn[in];
    g_Wprep[ob + 2 * 4096 + idx] = wv[5] * Wgc2[in];
    g_Wprep[ob + 3 * 4096 + idx] = wv[2] * Wgcn[in];
    g_Wprep[ob + 4 * 4096 + idx] = wv[4] * Wgin[in];
    g_Wprep[ob + 5 * 4096 + idx] = wv[6] * Wmlp[in];
    g_Wprep[ob + 6 * 4096 + idx] = wv[7] * 0.9f * Wgcnii[in];
}

// ------------------------- generic fp32 linear: Y = X@W (+pooled/bias), opt col stats -------------------------
__global__ __launch_bounds__(256)
void lin_kernel(const float* __restrict__ X, int ldx,
                const float* __restrict__ W, int ldw,
                float* __restrict__ Y, int ldy,
                int K, int M, int flags,
                const float* __restrict__ bias,
                const float* __restrict__ pooled,
                const float* __restrict__ w0) {
    __shared__ __align__(16) float Xs[32 * 132];
    __shared__ __align__(16) float Ws[32 * 64];
    int tid = threadIdx.x, tx = tid & 15, ty = tid >> 4;
    int rowbase = blockIdx.x * 128, colbase = blockIdx.y * 64;
    float acc[8][4];
#pragma unroll
    for (int i = 0; i < 8; i++)
#pragma unroll
        for (int j = 0; j < 4; j++) acc[i][j] = 0.f;

    for (int kc = 0; kc < K; kc += 32) {
        __syncthreads();
#pragma unroll
        for (int i = 0; i < 2; i++) {
            int idx4 = i * 256 + tid;
            int kk = idx4 >> 4, cc4 = (idx4 & 15) * 4;
            int gc = colbase + cc4;
            float4 w4 = make_float4(0.f, 0.f, 0.f, 0.f);
            if (gc < M) w4 = *(const float4*)&W[(size_t)(kc + kk) * ldw + gc];
            *(float4*)&Ws[kk * 64 + cc4] = w4;
        }
        {
            int kk = tid & 31, rb = (tid >> 5) * 4;
#pragma unroll
            for (int i = 0; i < 4; i++) {
                int rr = i * 32 + rb;
                float v[4];
#pragma unroll
                for (int q = 0; q < 4; q++) {
                    int gr = rowbase + rr + q;
                    v[q] = (gr < NN) ? X[(size_t)gr * ldx + kc + kk] : 0.f;
                }
                *(float4*)&Xs[kk * 132 + rr] = make_float4(v[0], v[1], v[2], v[3]);
            }
        }
        __syncthreads();
#pragma unroll 8
        for (int k = 0; k < 32; k++) {
            float4 a0 = *(const float4*)&Xs[k * 132 + ty * 8];
            float4 a1 = *(const float4*)&Xs[k * 132 + ty * 8 + 4];
            float4 b  = *(const float4*)&Ws[k * 64 + tx * 4];
            float ar[8] = {a0.x, a0.y, a0.z, a0.w, a1.x, a1.y, a1.z, a1.w};
            float br[4] = {b.x, b.y, b.z, b.w};
#pragma unroll
            for (int i = 0; i < 8; i++)
#pragma unroll
                for (int j = 0; j < 4; j++) acc[i][j] = fmaf(ar[i], br[j], acc[i][j]);
        }
    }

    int r0 = rowbase + ty * 8, c0 = colbase + tx * 4;
#pragma unroll
    for (int i = 0; i < 8; i++) {
        int r = r0 + i;
        if (r >= NN) continue;
#pragma unroll
        for (int j = 0; j < 4; j++) {
            int c = c0 + j;
            if (c >= M) continue;
            float v = acc[i][j];
            if (flags & F_POOL) v = fmaf(pooled[r], w0[c], v);
            if (flags & F_BIAS) v += bias[c];
            Y[(size_t)r * ldy + c] = v;
        }
    }

    if (flags & F_STATS) {
        __syncthreads();
#pragma unroll
        for (int j = 0; j < 4; j++) {
            float s = 0.f, s2 = 0.f;
#pragma unroll
            for (int i = 0; i < 8; i++) {
                int r = r0 + i;
                if (r < NN) { float v = acc[i][j]; s += v; s2 = fmaf(v, v, s2); }
            }
            Xs[(tx * 4 + j) * 16 + ty] = s;
            Ws[(tx * 4 + j) * 16 + ty] = s2;
        }
        __syncthreads();
        if (tid < 64) {
            float s = 0.f, s2 = 0.f;
#pragma unroll
            for (int t = 0; t < 16; t++) { s += Xs[tid * 16 + t]; s2 += Ws[tid * 16 + t]; }
            int c = colbase + tid;
            if (c < M) { atomicAdd(&g_colsum[c], s); atomicAdd(&g_colsq[c], s2); }
        }
    }
}

// ------------------------- batch norm helpers -------------------------
__global__ void zero_stats_kernel() {
    g_colsum[threadIdx.x] = 0.f;
    g_colsq[threadIdx.x]  = 0.f;
}

__global__ void bn_fin_kernel(int M) {
    int c = threadIdx.x;
    if (c >= M) return;
    float invN = 1.f / (float)NN;
    float mu  = g_colsum[c] * invN;
    float var = g_colsq[c] * invN - mu * mu;
    g_mu[c]  = mu;
    g_rsd[c] = rsqrtf(var + 1e-5f);
}

__global__ void bn_apply_kernel(const float* __restrict__ src, float* __restrict__ dst,
                                int total4, int M, int relu) {
    int i = blockIdx.x * blockDim.x + threadIdx.x;
    if (i >= total4) return;
    float4 v = ((const float4*)src)[i];
    int c = (i * 4) % M;
    v.x = (v.x - g_mu[c    ]) * g_rsd[c    ];
    v.y = (v.y - g_mu[c + 1]) * g_rsd[c + 1];
    v.z = (v.z - g_mu[c + 2]) * g_rsd[c + 2];
    v.w = (v.w - g_mu[c + 3]) * g_rsd[c + 3];
    if (relu) {
        v.x = fmaxf(v.x, 0.f); v.y = fmaxf(v.y, 0.f);
        v.z = fmaxf(v.z, 0.f); v.w = fmaxf(v.w, 0.f);
    }
    ((float4*)dst)[i] = v;
}

// ------------------------- CSR aggregation: s_sum + s_norm in one pass -------------------------
__global__ void agg_kernel(const float* __restrict__ h, int ldh,
                           float* __restrict__ oS, float* __restrict__ oN) {
    int w = (blockIdx.x * blockDim.x + threadIdx.x) >> 5;
    int lane = threadIdx.x & 31;
    if (w >= NN) return;
    int beg = g_rptr[w], end = g_rptr[w + 1];
    float sx = 0.f, sy = 0.f, nx = 0.f, ny = 0.f;
    for (int e = beg; e < end; e++) {
        int s = g_esrc[e];
        float wn = g_enorm[e];
        float2 v = *(const float2*)&h[(size_t)s * ldh + lane * 2];
        sx += v.x; sy += v.y;
        nx = fmaf(wn, v.x, nx); ny = fmaf(wn, v.y, ny);
    }
    *(float2*)&oS[(size_t)w * 64 + lane * 2] = make_float2(sx, sy);
    *(float2*)&oN[(size_t)w * 64 + lane * 2] = make_float2(nx, ny);
}

// ------------------------- fused mixed-op: 7 K=64 passes into one output -------------------------
__global__ __launch_bounds__(256)
void mixed_kernel(const float* __restrict__ h, int ldh,
                  const float* __restrict__ sS, const float* __restrict__ sN,
                  const float* __restrict__ Wp,
                  float* __restrict__ out, int ldy, int accum) {
    __shared__ __align__(16) float Xs[32 * 132];
    __shared__ __align__(16) float Ws[32 * 64];
    int tid = threadIdx.x, tx = tid & 15, ty = tid >> 4;
    int rowbase = blockIdx.x * 128;
    int r0 = rowbase + ty * 8;

    float acc[8][4];
    if (accum) {
#pragma unroll
        for (int i = 0; i < 8; i++) {
            int r = r0 + i;
            if (r < NN) {
                float4 v = *(const float4*)&out[(size_t)r * ldy + tx * 4];
                acc[i][0] = v.x; acc[i][1] = v.y; acc[i][2] = v.z; acc[i][3] = v.w;
            } else {
                acc[i][0] = acc[i][1] = acc[i][2] = acc[i][3] = 0.f;
            }
        }
    } else {
#pragma unroll
        for (int i = 0; i < 8; i++)
#pragma unroll
            for (int j = 0; j < 4; j++) acc[i][j] = 0.f;
    }

    for (int p = 0; p < 7; p++) {
        float pacc[8][4];
#pragma unroll
        for (int i = 0; i < 8; i++)
#pragma unroll
            for (int j = 0; j < 4; j++) pacc[i][j] = 0.f;

        for (int kc = 0; kc < 64; kc += 32) {
            __syncthreads();
#pragma unroll
            for (int i = 0; i < 2; i++) {
                int idx4 = i * 256 + tid;
                int kk = idx4 >> 4, cc4 = (idx4 & 15) * 4;
                *(float4*)&Ws[kk * 64 + cc4] =
                    *(const float4*)&Wp[p * 4096 + (kc + kk) * 64 + cc4];
            }
            {
                int kk = tid & 31, rb = (tid >> 5) * 4;
                int kg = kc + kk;
#pragma unroll
                for (int i = 0; i < 4; i++) {
                    int rr = i * 32 + rb;
                    float v[4];
#pragma unroll
                    for (int q = 0; q < 4; q++) {
                        int gr = rowbase + rr + q;
                        float val = 0.f;
                        if (gr < NN) {
                            size_t gi = (size_t)gr * ldh + kg;
                            size_t ai = (size_t)gr * 64 + kg;
                            switch (p) {
                                case 0: val = h[gi]; break;
                                case 1: val = sS[ai] * g_invdeg[gr]; break;
                                case 2: val = sS[ai]; break;
                                case 3: val = sN[ai]; break;
                                case 4: val = h[gi] + sS[ai]; break;
                                case 5: val = h[gi]; break;
                                default: val = sN[ai] + 0.11111111f * g_x0[ai]; break;
                            }
                        }
                        v[q] = val;
                    }
                    *(float4*)&Xs[kk * 132 + rr] = make_float4(v[0], v[1], v[2], v[3]);
                }
            }
            __syncthreads();
#pragma unroll 8
            for (int k = 0; k < 32; k++) {
                float4 a0 = *(const float4*)&Xs[k * 132 + ty * 8];
                float4 a1 = *(const float4*)&Xs[k * 132 + ty * 8 + 4];
                float4 b  = *(const float4*)&Ws[k * 64 + tx * 4];
                float ar[8] = {a0.x, a0.y, a0.z, a0.w, a1.x, a1.y, a1.z, a1.w};
                float br[4] = {b.x, b.y, b.z, b.w};
#pragma unroll
                for (int i = 0; i < 8; i++)
#pragma unroll
                    for (int j = 0; j < 4; j++) pacc[i][j] = fmaf(ar[i], br[j], pacc[i][j]);
            }
        }
        if (p >= 3) {
#pragma unroll
            for (int i = 0; i < 8; i++)
#pragma unroll
                for (int j = 0; j < 4; j++) acc[i][j] += fmaxf(pacc[i][j], 0.f);
        } else {
#pragma unroll
            for (int i = 0; i < 8; i++)
#pragma unroll
                for (int j = 0; j < 4; j++) acc[i][j] += pacc[i][j];
        }
    }

#pragma unroll
    for (int i = 0; i < 8; i++) {
        int r = r0 + i;
        if (r < NN)
            *(float4*)&out[(size_t)r * ldy + tx * 4] =
                make_float4(acc[i][0], acc[i][1], acc[i][2], acc[i][3]);
    }
}

// ------------------------- channel mean pooling -------------------------
__global__ void pooled_kernel(const float* __restrict__ h) {
    int w = (blockIdx.x * blockDim.x + threadIdx.x) >> 5;
    int lane = threadIdx.x & 31;
    if (w >= NN) return;
    const float* row = h + (size_t)w * 256;
    float s = 0.f;
#pragma unroll
    for (int i = 0; i < 8; i++) s += row[lane + i * 32];
#pragma unroll
    for (int off = 16; off > 0; off >>= 1) s += __shfl_xor_sync(0xffffffff, s, off);
    if (lane == 0) g_pooled[w] = s * (1.f / 256.f);
}

// ------------------------- host orchestration -------------------------
extern "C" void kernel_launch(void* const* d_in, const int* in_sizes, int n_in,
                              void* d_out, int out_size) {
    const float* x      = (const float*)d_in[0];
    const int*   ei     = (const int*)d_in[1];
    const float* alphas = (const float*)d_in[2];
    const float* stem_W = (const float*)d_in[3];
    const float* pre_W  = (const float*)d_in[4];
    const float* pre00  = (const float*)d_in[5];
    const float* pre10  = (const float*)d_in[6];
    const float* pre01  = (const float*)d_in[7];
    const float* pre11  = (const float*)d_in[8];
    const float* cls_W  = (const float*)d_in[17];
    const float* cls_b  = (const float*)d_in[18];
    float* out = (float*)d_out;

    float *stem, *cell, *ab, *x0p, *tmp, *aggS, *aggN, *prep, *pooledb;
    cudaGetSymbolAddress((void**)&stem,    g_stem);
    cudaGetSymbolAddress((void**)&cell,    g_cell);
    cudaGetSymbolAddress((void**)&ab,      g_ab);
    cudaGetSymbolAddress((void**)&x0p,     g_x0);
    cudaGetSymbolAddress((void**)&tmp,     g_tmp);
    cudaGetSymbolAddress((void**)&aggS,    g_aggS);
    cudaGetSymbolAddress((void**)&aggN,    g_aggN);
    cudaGetSymbolAddress((void**)&prep,    g_Wprep);
    cudaGetSymbolAddress((void**)&pooledb, g_pooled);
    float* cell0 = cell;
    float* cell1 = cell + (size_t)NN * 256;
    float* ab0 = ab;
    float* ab1 = ab + (size_t)NN * 64;

    // graph preprocessing
    zero_cnt_kernel<<<(NN + 255) / 256, 256>>>();
    deg_kernel<<<(EE + 255) / 256, 256>>>(ei + EE);
    scan_kernel<<<1, 1024>>>();
    scatter_kernel<<<(EE + 255) / 256, 256>>>(ei, ei + EE);

    // mixed-op weight prep
    softmax_kernel<<<1, 32>>>(alphas);
    prep_kernel<<<dim3(28, 16), 256>>>((const float*)d_in[9],  (const float*)d_in[10],
                                       (const float*)d_in[11], (const float*)d_in[12],
                                       (const float*)d_in[13], (const float*)d_in[14],
                                       (const float*)d_in[15], (const float*)d_in[16]);

    const int GR = (NN + 127) / 128;  // 391
    auto LIN = [&](const float* X, int ldx, const float* W, int ldw, float* Y, int ldy,
                   int K, int M, int flags, const float* bias, const float* pooled,
                   const float* w0) {
        dim3 grid(GR, (M + 63) / 64);
        lin_kernel<<<grid, 256>>>(X, ldx, W, ldw, Y, ldy, K, M, flags, bias, pooled, w0);
    };
    auto BNL = [&](const float* X, int ldx, const float* W, float* dst, int K, int M, int relu) {
        zero_stats_kernel<<<1, 256>>>();
        LIN(X, ldx, W, M, tmp, M, K, M, F_STATS, nullptr, nullptr, nullptr);
        bn_fin_kernel<<<1, 256>>>(M);
        int t4 = NN * M / 4;
        bn_apply_kernel<<<(t4 + 255) / 256, 256>>>(tmp, dst, t4, M, relu);
    };

    BNL(x, 128, stem_W, stem, 128, 192, 0);   // stem [N,192], no relu
    BNL(x, 128, pre_W,  x0p,  128, 64, 1);    // x0 [N,64], relu

    const int AGGB = (NN * 32 + 255) / 256;   // warp per node
    for (int ci = 0; ci < 2; ci++) {
        const float* p0 = ci ? pre01 : pre00;
        const float* p1 = ci ? pre11 : pre10;
        const float* s1p = ci ? cell0 : stem;
        int lds1 = ci ? 256 : 192;
        float* co = ci ? cell1 : cell0;

        BNL(stem, 192, p0, ab0, 192, 64, 1);
        BNL(s1p, lds1, p1, ab1, lds1, 64, 1);

        auto stptr = [&](int j) -> float* { return j == 0 ? ab0 : (j == 1 ? ab1 : co + (j - 2) * 64); };
        auto stld  = [&](int j) -> int    { return j < 2 ? 64 : 256; };

        agg_kernel<<<AGGB, 256>>>(stptr(0), 64, aggS + 0 * (size_t)NN * 64, aggN + 0 * (size_t)NN * 64);
        agg_kernel<<<AGGB, 256>>>(stptr(1), 64, aggS + 1 * (size_t)NN * 64, aggN + 1 * (size_t)NN * 64);

        int offset = 0;
        for (int step = 0; step < 4; step++) {
            int nst = 2 + step;
            if (step > 0) {
                int jn = nst - 1;  // newest state (2,3,4)
                agg_kernel<<<AGGB, 256>>>(stptr(jn), stld(jn),
                                          aggS + (size_t)jn * NN * 64, aggN + (size_t)jn * NN * 64);
            }
            for (int j = 0; j < nst; j++) {
                int slot = ci * 14 + offset + j;
                mixed_kernel<<<GR, 256>>>(stptr(j), stld(j),
                                          aggS + (size_t)j * NN * 64, aggN + (size_t)j * NN * 64,
                                          prep + (size_t)slot * 7 * 4096,
                                          stptr(nst), 256, j > 0 ? 1 : 0);
            }
            offset += nst;
        }
    }

    // classifier: logits = pooled*cls_W[0] + s1 @ cls_W[1:] + b
    pooled_kernel<<<AGGB, 256>>>(cell1);
    LIN(cell1, 256, cls_W + 40, 40, out, 40, 256, 40, F_POOL | F_BIAS, cls_b, pooledb, cls_W);
}

// round 8
// speedup vs baseline: 1.4033x; 1.4033x over previous
#include <cuda_runtime.h>
#include <math.h>

#define NN 50000
#define EE 800000
#define F_STATS 1
#define F_BIAS  2
#define F_POOL  4

// ------------------------- static device scratch (zero-init BSS) -------------------------
__device__ float g_stem[NN * 192];
__device__ float g_cell[2][NN * 256];
__device__ float g_ab[2][NN * 64];
__device__ float g_x0[NN * 64];
__device__ float g_tmp[NN * 192];
// derived per-state arrays: kind 0=mean, 1=sum, 2=norm, 3=h+sum, 4=norm+x0/9
__device__ float g_der[5][5][NN * 64];
__device__ float g_enorm[EE];
__device__ int   g_esrc[EE];
__device__ int   g_cnt[NN];
__device__ int   g_rptr[NN + 1];
__device__ int   g_fill[NN];
__device__ float g_invdeg[NN];
__device__ float g_invsqrt[NN];
__device__ float g_pooled[NN];
__device__ float g_colsum[256];
__device__ float g_colsq[256];
__device__ float g_mu[256];
__device__ float g_rsd[256];
__device__ float g_wmix[14 * 8];
__device__ float g_Wprep[28 * 7 * 4096];

// ------------------------- graph preprocessing -------------------------
__global__ void zero_cnt_kernel() {
    int i = blockIdx.x * blockDim.x + threadIdx.x;
    if (i < NN) g_cnt[i] = 0;
}

__global__ void deg_kernel(const int* __restrict__ dst) {
    int e = blockIdx.x * blockDim.x + threadIdx.x;
    if (e < EE) atomicAdd(&g_cnt[dst[e]], 1);
}

__global__ void scan_kernel() {
    __shared__ int sh[1024];
    int carry = 0;
    for (int base = 0; base < NN; base += 1024) {
        int i = base + (int)threadIdx.x;
        int v = (i < NN) ? g_cnt[i] : 0;
        sh[threadIdx.x] = v;
        __syncthreads();
        for (int off = 1; off < 1024; off <<= 1) {
            int t = (threadIdx.x >= off) ? sh[threadIdx.x - off] : 0;
            __syncthreads();
            sh[threadIdx.x] += t;
            __syncthreads();
        }
        int incl = sh[threadIdx.x];
        if (i < NN) {
            int excl = carry + incl - v;
            g_rptr[i] = excl;
            g_fill[i] = excl;
            float d = (float)(v > 0 ? v : 1);
            g_invdeg[i]  = 1.0f / d;
            g_invsqrt[i] = rsqrtf(d);
        }
        carry += sh[1023];
        __syncthreads();
    }
    if (threadIdx.x == 0) g_rptr[NN] = carry;
}

__global__ void scatter_kernel(const int* __restrict__ src, const int* __restrict__ dst) {
    int e = blockIdx.x * blockDim.x + threadIdx.x;
    if (e >= EE) return;
    int s = src[e], d = dst[e];
    int pos = atomicAdd(&g_fill[d], 1);
    g_esrc[pos]  = s;
    g_enorm[pos] = g_invsqrt[s] * g_invsqrt[d];
}

// ------------------------- alpha softmax + fused weight prep -------------------------
__global__ void softmax_kernel(const float* __restrict__ a) {
    int r = threadIdx.x;
    if (r >= 14) return;
    float m = -1e30f;
    for (int j = 0; j < 8; j++) m = fmaxf(m, a[r * 8 + j]);
    float e[8], s = 0.f;
    for (int j = 0; j < 8; j++) { e[j] = expf(a[r * 8 + j] - m); s += e[j]; }
    float inv = 1.f / s;
    for (int j = 0; j < 8; j++) g_wmix[r * 8 + j] = e[j] * inv;
}

__global__ void prep_kernel(const float* __restrict__ Wgcn, const float* __restrict__ Wss,
                            const float* __restrict__ Wsn,  const float* __restrict__ Wgin,
                            const float* __restrict__ Wgc1, const float* __restrict__ Wgc2,
                            const float* __restrict__ Wmlp, const float* __restrict__ Wgcnii) {
    int slot = blockIdx.x;                       // ci*14 + ej
    int ej   = slot % 14;
    int idx  = blockIdx.y * 256 + threadIdx.x;   // 0..4095
    int r = idx >> 6, c = idx & 63;
    const float* wv = g_wmix + ej * 8;
    size_t in = (size_t)slot * 4096 + idx;
    size_t ob = (size_t)slot * 7 * 4096;
    g_Wprep[ob + 0 * 4096 + idx] = wv[1] * (r == c ? 1.f : 0.f) + wv[3] * Wss[in] + wv[5] * Wgc1[in];
    g_Wprep[ob + 1 * 4096 + idx] = wv[3] * Wsn[in];
    g_Wprep[ob + 2 * 4096 + idx] = wv[5] * Wgc2[in];
    g_Wprep[ob + 3 * 4096 + idx] = wv[2] * Wgcn[in];
    g_Wprep[ob + 4 * 4096 + idx] = wv[4] * Wgin[in];
    g_Wprep[ob + 5 * 4096 + idx] = wv[6] * Wmlp[in];
    g_Wprep[ob + 6 * 4096 + idx] = wv[7] * 0.9f * Wgcnii[in];
}

// ------------------------- generic fp32 linear (vectorized loads) -------------------------
__global__ __launch_bounds__(256)
void lin_kernel(const float* __restrict__ X, int ldx,
                const float* __restrict__ W, int ldw,
                float* __restrict__ Y, int ldy,
                int K, int M, int flags,
                const float* __restrict__ bias,
                const float* __restrict__ pooled,
                const float* __restrict__ w0) {
    __shared__ __align__(16) float Xs[32 * 132];
    __shared__ __align__(16) float Ws[32 * 64];
    int tid = threadIdx.x, tx = tid & 15, ty = tid >> 4;
    int rowbase = blockIdx.x * 128, colbase = blockIdx.y * 64;
    float acc[8][4];
#pragma unroll
    for (int i = 0; i < 8; i++)
#pragma unroll
        for (int j = 0; j < 4; j++) acc[i][j] = 0.f;

    for (int kc = 0; kc < K; kc += 32) {
        __syncthreads();
#pragma unroll
        for (int i = 0; i < 2; i++) {
            int idx = i * 256 + tid;
            int kk = idx >> 4, c4 = (idx & 15) * 4;
            int gc = colbase + c4;
            float4 w4 = make_float4(0.f, 0.f, 0.f, 0.f);
            if (gc < M) w4 = *(const float4*)&W[(size_t)(kc + kk) * ldw + gc];
            *(float4*)&Ws[kk * 64 + c4] = w4;
        }
#pragma unroll
        for (int i = 0; i < 4; i++) {
            int idx = i * 256 + tid;   // 0..1023
            int row = idx >> 3, k4 = idx & 7;
            int gr = rowbase + row;
            float4 v = make_float4(0.f, 0.f, 0.f, 0.f);
            if (gr < NN) v = *(const float4*)&X[(size_t)gr * ldx + kc + k4 * 4];
            int kb = k4 * 4;
            Xs[(kb + 0) * 132 + row] = v.x;
            Xs[(kb + 1) * 132 + row] = v.y;
            Xs[(kb + 2) * 132 + row] = v.z;
            Xs[(kb + 3) * 132 + row] = v.w;
        }
        __syncthreads();
#pragma unroll 8
        for (int k = 0; k < 32; k++) {
            float4 a0 = *(const float4*)&Xs[k * 132 + ty * 8];
            float4 a1 = *(const float4*)&Xs[k * 132 + ty * 8 + 4];
            float4 b  = *(const float4*)&Ws[k * 64 + tx * 4];
            float ar[8] = {a0.x, a0.y, a0.z, a0.w, a1.x, a1.y, a1.z, a1.w};
            float br[4] = {b.x, b.y, b.z, b.w};
#pragma unroll
            for (int i = 0; i < 8; i++)
#pragma unroll
                for (int j = 0; j < 4; j++) acc[i][j] = fmaf(ar[i], br[j], acc[i][j]);
        }
    }

    int r0 = rowbase + ty * 8, c0 = colbase + tx * 4;
#pragma unroll
    for (int i = 0; i < 8; i++) {
        int r = r0 + i;
        if (r >= NN) continue;
#pragma unroll
        for (int j = 0; j < 4; j++) {
            int c = c0 + j;
            if (c >= M) continue;
            float v = acc[i][j];
            if (flags & F_POOL) v = fmaf(pooled[r], w0[c], v);
            if (flags & F_BIAS) v += bias[c];
            Y[(size_t)r * ldy + c] = v;
        }
    }

    if (flags & F_STATS) {
        __syncthreads();
#pragma unroll
        for (int j = 0; j < 4; j++) {
            float s = 0.f, s2 = 0.f;
#pragma unroll
            for (int i = 0; i < 8; i++) {
                int r = r0 + i;
                if (r < NN) { float v = acc[i][j]; s += v; s2 = fmaf(v, v, s2); }
            }
            Xs[(tx * 4 + j) * 16 + ty] = s;
            Ws[(tx * 4 + j) * 16 + ty] = s2;
        }
        __syncthreads();
        if (tid < 64) {
            float s = 0.f, s2 = 0.f;
#pragma unroll
            for (int t = 0; t < 16; t++) { s += Xs[tid * 16 + t]; s2 += Ws[tid * 16 + t]; }
            int c = colbase + tid;
            if (c < M) { atomicAdd(&g_colsum[c], s); atomicAdd(&g_colsq[c], s2); }
        }
    }
}

// ------------------------- batch norm helpers -------------------------
__global__ void zero_stats_kernel() {
    g_colsum[threadIdx.x] = 0.f;
    g_colsq[threadIdx.x]  = 0.f;
}

__global__ void bn_fin_kernel(int M) {
    int c = threadIdx.x;
    if (c >= M) return;
    float invN = 1.f / (float)NN;
    float mu  = g_colsum[c] * invN;
    float var = g_colsq[c] * invN - mu * mu;
    g_mu[c]  = mu;
    g_rsd[c] = rsqrtf(var + 1e-5f);
}

__global__ void bn_apply_kernel(const float* __restrict__ src, float* __restrict__ dst,
                                int total4, int M, int relu) {
    int i = blockIdx.x * blockDim.x + threadIdx.x;
    if (i >= total4) return;
    float4 v = ((const float4*)src)[i];
    int c = (i * 4) % M;
    v.x = (v.x - g_mu[c    ]) * g_rsd[c    ];
    v.y = (v.y - g_mu[c + 1]) * g_rsd[c + 1];
    v.z = (v.z - g_mu[c + 2]) * g_rsd[c + 2];
    v.w = (v.w - g_mu[c + 3]) * g_rsd[c + 3];
    if (relu) {
        v.x = fmaxf(v.x, 0.f); v.y = fmaxf(v.y, 0.f);
        v.z = fmaxf(v.z, 0.f); v.w = fmaxf(v.w, 0.f);
    }
    ((float4*)dst)[i] = v;
}

// ------------------------- CSR aggregation: writes 5 derived arrays -------------------------
__global__ void agg_kernel(const float* __restrict__ h, int ldh, int j) {
    int w = (blockIdx.x * blockDim.x + threadIdx.x) >> 5;
    int lane = threadIdx.x & 31;
    if (w >= NN) return;
    int beg = g_rptr[w], end = g_rptr[w + 1];
    float sx = 0.f, sy = 0.f, nx = 0.f, ny = 0.f;
    for (int e = beg; e < end; e++) {
        int s = g_esrc[e];
        float wn = g_enorm[e];
        float2 v = *(const float2*)&h[(size_t)s * ldh + lane * 2];
        sx += v.x; sy += v.y;
        nx = fmaf(wn, v.x, nx); ny = fmaf(wn, v.y, ny);
    }
    float2 hv = *(const float2*)&h[(size_t)w * ldh + lane * 2];
    float2 xv = *(const float2*)&g_x0[(size_t)w * 64 + lane * 2];
    float id = g_invdeg[w];
    size_t o = (size_t)w * 64 + lane * 2;
    *(float2*)&g_der[0][j][o] = make_float2(sx * id, sy * id);                    // mean
    *(float2*)&g_der[1][j][o] = make_float2(sx, sy);                              // sum
    *(float2*)&g_der[2][j][o] = make_float2(nx, ny);                              // norm
    *(float2*)&g_der[3][j][o] = make_float2(hv.x + sx, hv.y + sy);                // h+sum
    *(float2*)&g_der[4][j][o] = make_float2(fmaf(0.11111111f, xv.x, nx),
                                            fmaf(0.11111111f, xv.y, ny));         // norm+x0/9
}

// ------------------------- fused per-step mixed-op: all states, 7 passes each -------------------------
struct StepArgs {
    const float* h[5];
    int ldh[5];
    const float* wbase;
    float* out;     // ld 256, 64-col slice
    int nst;
};

__global__ __launch_bounds__(256)
void step_kernel(StepArgs A) {
    __shared__ __align__(16) float Xs[32 * 132];
    __shared__ __align__(16) float Ws[32 * 64];
    int tid = threadIdx.x, tx = tid & 15, ty = tid >> 4;
    int rowbase = blockIdx.x * 128;
    int r0 = rowbase + ty * 8;

    float acc[8][4];
#pragma unroll
    for (int i = 0; i < 8; i++)
#pragma unroll
        for (int j = 0; j < 4; j++) acc[i][j] = 0.f;

    for (int j = 0; j < A.nst; j++) {
        const float* hj = A.h[j];
        int ldh = A.ldh[j];
        const float* wj = A.wbase + (size_t)j * 7 * 4096;
#pragma unroll
        for (int p = 0; p < 7; p++) {
            const float* src;
            int ld;
            switch (p) {
                case 0:  src = hj;              ld = ldh; break;
                case 1:  src = &g_der[0][j][0]; ld = 64;  break;
                case 2:  src = &g_der[1][j][0]; ld = 64;  break;
                case 3:  src = &g_der[2][j][0]; ld = 64;  break;
                case 4:  src = &g_der[3][j][0]; ld = 64;  break;
                case 5:  src = hj;              ld = ldh; break;
                default: src = &g_der[4][j][0]; ld = 64;  break;
            }
            float pacc[8][4];
#pragma unroll
            for (int i = 0; i < 8; i++)
#pragma unroll
                for (int q = 0; q < 4; q++) pacc[i][q] = 0.f;

            for (int kc = 0; kc < 64; kc += 32) {
                __syncthreads();
#pragma unroll
                for (int i = 0; i < 2; i++) {
                    int idx = i * 256 + tid;
                    int kk = idx >> 4, c4 = (idx & 15) * 4;
                    *(float4*)&Ws[kk * 64 + c4] =
                        *(const float4*)&wj[(size_t)p * 4096 + (kc + kk) * 64 + c4];
                }
#pragma unroll
                for (int i = 0; i < 4; i++) {
                    int idx = i * 256 + tid;
                    int row = idx >> 3, k4 = idx & 7;
                    int gr = rowbase + row;
                    float4 v = make_float4(0.f, 0.f, 0.f, 0.f);
                    if (gr < NN) v = *(const float4*)&src[(size_t)gr * ld + kc + k4 * 4];
                    int kb = k4 * 4;
                    Xs[(kb + 0) * 132 + row] = v.x;
                    Xs[(kb + 1) * 132 + row] = v.y;
                    Xs[(kb + 2) * 132 + row] = v.z;
                    Xs[(kb + 3) * 132 + row] = v.w;
                }
                __syncthreads();
#pragma unroll 8
                for (int k = 0; k < 32; k++) {
                    float4 a0 = *(const float4*)&Xs[k * 132 + ty * 8];
                    float4 a1 = *(const float4*)&Xs[k * 132 + ty * 8 + 4];
                    float4 b  = *(const float4*)&Ws[k * 64 + tx * 4];
                    float ar[8] = {a0.x, a0.y, a0.z, a0.w, a1.x, a1.y, a1.z, a1.w};
                    float br[4] = {b.x, b.y, b.z, b.w};
#pragma unroll
                    for (int i = 0; i < 8; i++)
#pragma unroll
                        for (int q = 0; q < 4; q++) pacc[i][q] = fmaf(ar[i], br[q], pacc[i][q]);
                }
            }
            if (p >= 3) {
#pragma unroll
                for (int i = 0; i < 8; i++)
#pragma unroll
                    for (int q = 0; q < 4; q++) acc[i][q] += fmaxf(pacc[i][q], 0.f);
            } else {
#pragma unroll
                for (int i = 0; i < 8; i++)
#pragma unroll
                    for (int q = 0; q < 4; q++) acc[i][q] += pacc[i][q];
            }
        }
    }

#pragma unroll
    for (int i = 0; i < 8; i++) {
        int r = r0 + i;
        if (r < NN)
            *(float4*)&A.out[(size_t)r * 256 + tx * 4] =
                make_float4(acc[i][0], acc[i][1], acc[i][2], acc[i][3]);
    }
}

// ------------------------- channel mean pooling -------------------------
__global__ void pooled_kernel(const float* __restrict__ h) {
    int w = (blockIdx.x * blockDim.x + threadIdx.x) >> 5;
    int lane = threadIdx.x & 31;
    if (w >= NN) return;
    const float* row = h + (size_t)w * 256;
    float s = 0.f;
#pragma unroll
    for (int i = 0; i < 8; i++) s += row[lane + i * 32];
#pragma unroll
    for (int off = 16; off > 0; off >>= 1) s += __shfl_xor_sync(0xffffffff, s, off);
    if (lane == 0) g_pooled[w] = s * (1.f / 256.f);
}

// ------------------------- host orchestration -------------------------
extern "C" void kernel_launch(void* const* d_in, const int* in_sizes, int n_in,
                              void* d_out, int out_size) {
    const float* x      = (const float*)d_in[0];
    const int*   ei     = (const int*)d_in[1];
    const float* alphas = (const float*)d_in[2];
    const float* stem_W = (const float*)d_in[3];
    const float* pre_W  = (const float*)d_in[4];
    const float* pre00  = (const float*)d_in[5];
    const float* pre10  = (const float*)d_in[6];
    const float* pre01  = (const float*)d_in[7];
    const float* pre11  = (const float*)d_in[8];
    const float* cls_W  = (const float*)d_in[17];
    const float* cls_b  = (const float*)d_in[18];
    float* out = (float*)d_out;

    float *stem, *cell, *ab, *x0p, *tmp, *prep, *pooledb;
    cudaGetSymbolAddress((void**)&stem,    g_stem);
    cudaGetSymbolAddress((void**)&cell,    g_cell);
    cudaGetSymbolAddress((void**)&ab,      g_ab);
    cudaGetSymbolAddress((void**)&x0p,     g_x0);
    cudaGetSymbolAddress((void**)&tmp,     g_tmp);
    cudaGetSymbolAddress((void**)&prep,    g_Wprep);
    cudaGetSymbolAddress((void**)&pooledb, g_pooled);
    float* cell0 = cell;
    float* cell1 = cell + (size_t)NN * 256;
    float* ab0 = ab;
    float* ab1 = ab + (size_t)NN * 64;

    // graph preprocessing
    zero_cnt_kernel<<<(NN + 255) / 256, 256>>>();
    deg_kernel<<<(EE + 255) / 256, 256>>>(ei + EE);
    scan_kernel<<<1, 1024>>>();
    scatter_kernel<<<(EE + 255) / 256, 256>>>(ei, ei + EE);

    // mixed-op weight prep
    softmax_kernel<<<1, 32>>>(alphas);
    prep_kernel<<<dim3(28, 16), 256>>>((const float*)d_in[9],  (const float*)d_in[10],
                                       (const float*)d_in[11], (const float*)d_in[12],
                                       (const float*)d_in[13], (const float*)d_in[14],
                                       (const float*)d_in[15], (const float*)d_in[16]);

    const int GR = (NN + 127) / 128;  // 391
    auto LIN = [&](const float* X, int ldx, const float* W, int ldw, float* Y, int ldy,
                   int K, int M, int flags, const float* bias, const float* pooled,
                   const float* w0) {
        dim3 grid(GR, (M + 63) / 64);
        lin_kernel<<<grid, 256>>>(X, ldx, W, ldw, Y, ldy, K, M, flags, bias, pooled, w0);
    };
    auto BNL = [&](const float* X, int ldx, const float* W, float* dst, int K, int M, int relu) {
        zero_stats_kernel<<<1, 256>>>();
        LIN(X, ldx, W, M, tmp, M, K, M, F_STATS, nullptr, nullptr, nullptr);
        bn_fin_kernel<<<1, 256>>>(M);
        int t4 = NN * M / 4;
        bn_apply_kernel<<<(t4 + 255) / 256, 256>>>(tmp, dst, t4, M, relu);
    };

    BNL(x, 128, stem_W, stem, 128, 192, 0);   // stem [N,192], no relu
    BNL(x, 128, pre_W,  x0p,  128, 64, 1);    // x0 [N,64], relu

    const int AGGB = (NN * 32 + 255) / 256;   // warp per node
    for (int ci = 0; ci < 2; ci++) {
        const float* p0 = ci ? pre01 : pre00;
        const float* p1 = ci ? pre11 : pre10;
        const float* s1p = ci ? cell0 : stem;
        int lds1 = ci ? 256 : 192;
        float* co = ci ? cell1 : cell0;

        BNL(stem, 192, p0, ab0, 192, 64, 1);
        BNL(s1p, lds1, p1, ab1, lds1, 64, 1);

        auto stptr = [&](int j) -> float* { return j == 0 ? ab0 : (j == 1 ? ab1 : co + (j - 2) * 64); };
        auto stld  = [&](int j) -> int    { return j < 2 ? 64 : 256; };

        agg_kernel<<<AGGB, 256>>>(stptr(0), 64, 0);
        agg_kernel<<<AGGB, 256>>>(stptr(1), 64, 1);

        int offset = 0;
        for (int step = 0; step < 4; step++) {
            int nst = 2 + step;
            if (step > 0) {
                int jn = nst - 1;  // newest state (2,3,4)
                agg_kernel<<<AGGB, 256>>>(stptr(jn), stld(jn), jn);
            }
            StepArgs A;
            for (int j = 0; j < nst; j++) { A.h[j] = stptr(j); A.ldh[j] = stld(j); }
            for (int j = nst; j < 5; j++) { A.h[j] = stptr(0); A.ldh[j] = 64; }
            A.wbase = prep + (size_t)(ci * 14 + offset) * 7 * 4096;
            A.out   = stptr(nst);
            A.nst   = nst;
            step_kernel<<<GR, 256>>>(A);
            offset += nst;
        }
    }

    // classifier: logits = pooled*cls_W[0] + s1 @ cls_W[1:] + b
    pooled_kernel<<<AGGB, 256>>>(cell1);
    LIN(cell1, 256, cls_W + 40, 40, out, 40, 256, 40, F_POOL | F_BIAS, cls_b, pooledb, cls_W);
}